// round 3
// baseline (speedup 1.0000x reference)
#include <cuda_runtime.h>
#include <cstdint>

// Problem constants
#define BATCH 4
#define SEQ   4096
#define EMB   1024
#define HD    64
#define MTOT  (BATCH * SEQ)   // 16384 rows

// -------- scratch (device globals; no allocation allowed) --------
__device__ float g_Q[(size_t)MTOT * HD];
__device__ float g_K[(size_t)MTOT * HD];
__device__ float g_V[(size_t)MTOT * HD];

__device__ __forceinline__ float neg_inf() { return __int_as_float(0xff800000); }

// =====================================================================
// Kernel 1: QKV projection.  C[m,n] = sum_k x[m,k] * W[k,n]
// Tile: 64(M) x 64(N), K-chunks of 32. 128 threads, 8x4 micro-tile.
// grid = (MTOT/64, 3)  -> y selects (Wq->Q, Wk->K, Wv->V)
// =====================================================================
__global__ __launch_bounds__(128) void qkv_gemm(const float* __restrict__ x,
                                                const float* __restrict__ Wq,
                                                const float* __restrict__ Wk,
                                                const float* __restrict__ Wv) {
    __shared__ float xs[64][33];   // pad 33: conflict-free scalar access
    __shared__ float ws[32][68];   // pad 68: float4-aligned rows

    const float* W;
    float* out;
    if (blockIdx.y == 0)      { W = Wq; out = g_Q; }
    else if (blockIdx.y == 1) { W = Wk; out = g_K; }
    else                      { W = Wv; out = g_V; }

    const int m0  = blockIdx.x * 64;
    const int tid = threadIdx.x;
    const int tx  = tid & 15;     // 0..15 -> 4 output cols each
    const int ty  = tid >> 4;     // 0..7  -> 8 output rows each

    float acc[8][4];
#pragma unroll
    for (int i = 0; i < 8; i++)
#pragma unroll
        for (int j = 0; j < 4; j++) acc[i][j] = 0.f;

    for (int kc = 0; kc < EMB; kc += 32) {
        __syncthreads();
        // load x tile 64x32 (coalesced float4 -> scalar smem stores)
#pragma unroll
        for (int it = 0; it < 4; it++) {
            int flat = it * 128 + tid;          // 512 float4
            int r = flat >> 3, c4 = flat & 7;
            float4 v = *(const float4*)&x[(size_t)(m0 + r) * EMB + kc + c4 * 4];
            xs[r][c4 * 4 + 0] = v.x; xs[r][c4 * 4 + 1] = v.y;
            xs[r][c4 * 4 + 2] = v.z; xs[r][c4 * 4 + 3] = v.w;
        }
        // load W chunk 32x64 (float4 both sides)
#pragma unroll
        for (int it = 0; it < 4; it++) {
            int flat = it * 128 + tid;          // 512 float4
            int k = flat >> 4, n4 = flat & 15;
            float4 v = *(const float4*)&W[(size_t)(kc + k) * HD + n4 * 4];
            *(float4*)&ws[k][n4 * 4] = v;
        }
        __syncthreads();

#pragma unroll
        for (int k = 0; k < 32; k++) {
            float a[8];
#pragma unroll
            for (int i = 0; i < 8; i++) a[i] = xs[ty * 8 + i][k];
            float4 w = *(const float4*)&ws[k][tx * 4];
#pragma unroll
            for (int i = 0; i < 8; i++) {
                acc[i][0] += a[i] * w.x;
                acc[i][1] += a[i] * w.y;
                acc[i][2] += a[i] * w.z;
                acc[i][3] += a[i] * w.w;
            }
        }
    }

#pragma unroll
    for (int i = 0; i < 8; i++) {
        float4 v = make_float4(acc[i][0], acc[i][1], acc[i][2], acc[i][3]);
        *(float4*)&out[(size_t)(m0 + ty * 8 + i) * HD + tx * 4] = v;
    }
}

// =====================================================================
// Kernel 2: causal flash attention.
// BLOCK_M = BLOCK_N = 64, 256 threads, 4x4 micro-tiles.
// P-tile shares the K smem buffer (K reads finish before P writes).
// Online softmax in exp2 domain; 1/sqrt(E)*log2(e) pre-folded into Q.
// grid = 256 CTAs, longest q-tiles launched first for balance.
// =====================================================================
__global__ __launch_bounds__(256) void attn_kernel(float* __restrict__ out) {
    extern __shared__ float sm[];
    float (*Qs)[65]  = (float (*)[65])sm;                  // 64x65
    float (*KPs)[65] = (float (*)[65])(sm + 64 * 65);      // 64x65 (K then P)
    float (*Vs)[64]  = (float (*)[64])(sm + 2 * 64 * 65);  // 64x64

    const int bid = blockIdx.x;
    const int b   = bid & 3;
    const int qt  = (SEQ / 64 - 1) - (bid >> 2);   // longest-first
    const int q0  = qt * 64;

    const float* Qg = g_Q + (size_t)b * SEQ * HD;
    const float* Kg = g_K + (size_t)b * SEQ * HD;
    const float* Vg = g_V + (size_t)b * SEQ * HD;

    const int tid = threadIdx.x;
    const int tx  = tid & 15;    // cols: tx*4 .. tx*4+3
    const int ty  = tid >> 4;    // rows: ty*4 .. ty*4+3

    // 1/sqrt(E) * log2(e)
    const float qscale = 0.03125f * 1.44269504088896340736f;

    // load Q tile (scaled)
#pragma unroll
    for (int it = 0; it < 4; it++) {
        int flat = it * 256 + tid;            // 1024 float4
        int r = flat >> 4, h4 = flat & 15;
        float4 v = *(const float4*)&Qg[(size_t)(q0 + r) * HD + h4 * 4];
        Qs[r][h4 * 4 + 0] = v.x * qscale; Qs[r][h4 * 4 + 1] = v.y * qscale;
        Qs[r][h4 * 4 + 2] = v.z * qscale; Qs[r][h4 * 4 + 3] = v.w * qscale;
    }

    float m_i[4], l_i[4], acc[4][4];
#pragma unroll
    for (int i = 0; i < 4; i++) {
        m_i[i] = neg_inf();
        l_i[i] = 0.f;
#pragma unroll
        for (int j = 0; j < 4; j++) acc[i][j] = 0.f;
    }

    const int nblocks = q0 / 64 + 1;
    for (int blk = 0; blk < nblocks; blk++) {
        const int n0 = blk * 64;
        __syncthreads();   // prev PV done reading KPs/Vs; Qs ready on 1st iter
        // load K (scalar into pad-65) and V (float4)
#pragma unroll
        for (int it = 0; it < 4; it++) {
            int flat = it * 256 + tid;
            int n = flat >> 4, h4 = flat & 15;
            float4 kv = *(const float4*)&Kg[(size_t)(n0 + n) * HD + h4 * 4];
            KPs[n][h4 * 4 + 0] = kv.x; KPs[n][h4 * 4 + 1] = kv.y;
            KPs[n][h4 * 4 + 2] = kv.z; KPs[n][h4 * 4 + 3] = kv.w;
            float4 vv = *(const float4*)&Vg[(size_t)(n0 + n) * HD + h4 * 4];
            *(float4*)&Vs[n][h4 * 4] = vv;
        }
        __syncthreads();

        // S = Q K^T (scaled) : s[i][j] = sum_h Qs[r][h] * K[c][h]
        float s[4][4];
#pragma unroll
        for (int i = 0; i < 4; i++)
#pragma unroll
            for (int j = 0; j < 4; j++) s[i][j] = 0.f;
#pragma unroll
        for (int h = 0; h < HD; h++) {
            float a[4], kk[4];
#pragma unroll
            for (int i = 0; i < 4; i++) a[i] = Qs[ty * 4 + i][h];
#pragma unroll
            for (int j = 0; j < 4; j++) kk[j] = KPs[tx * 4 + j][h];
#pragma unroll
            for (int i = 0; i < 4; i++)
#pragma unroll
                for (int j = 0; j < 4; j++) s[i][j] += a[i] * kk[j];
        }

        // causal mask only on the diagonal block (n0 == q0)
        if (blk == nblocks - 1) {
#pragma unroll
            for (int i = 0; i < 4; i++)
#pragma unroll
                for (int j = 0; j < 4; j++)
                    if (tx * 4 + j > ty * 4 + i) s[i][j] = neg_inf();
        }

        __syncthreads();   // everyone done reading K before P overwrites it

        // online softmax per row; write P into KPs
#pragma unroll
        for (int i = 0; i < 4; i++) {
            float mloc = fmaxf(fmaxf(s[i][0], s[i][1]), fmaxf(s[i][2], s[i][3]));
#pragma unroll
            for (int off = 8; off >= 1; off >>= 1)
                mloc = fmaxf(mloc, __shfl_xor_sync(0xffffffffu, mloc, off));
            float mnew = fmaxf(m_i[i], mloc);
            float corr = exp2f(m_i[i] - mnew);
            float lsum = 0.f;
            float p[4];
#pragma unroll
            for (int j = 0; j < 4; j++) { p[j] = exp2f(s[i][j] - mnew); lsum += p[j]; }
#pragma unroll
            for (int off = 8; off >= 1; off >>= 1)
                lsum += __shfl_xor_sync(0xffffffffu, lsum, off);
            l_i[i] = l_i[i] * corr + lsum;
            m_i[i] = mnew;
#pragma unroll
            for (int j = 0; j < 4; j++) acc[i][j] *= corr;
#pragma unroll
            for (int j = 0; j < 4; j++) KPs[ty * 4 + i][tx * 4 + j] = p[j];
        }
        __syncthreads();   // P visible

        // O += P V : acc[i][j] += sum_n P[r][n] * V[n][c]
#pragma unroll
        for (int n = 0; n < 64; n++) {
            float pp[4];
#pragma unroll
            for (int i = 0; i < 4; i++) pp[i] = KPs[ty * 4 + i][n];
            float4 vv = *(const float4*)&Vs[n][tx * 4];
#pragma unroll
            for (int i = 0; i < 4; i++) {
                acc[i][0] += pp[i] * vv.x;
                acc[i][1] += pp[i] * vv.y;
                acc[i][2] += pp[i] * vv.z;
                acc[i][3] += pp[i] * vv.w;
            }
        }
    }

    // epilogue: normalize and store
#pragma unroll
    for (int i = 0; i < 4; i++) {
        float inv = 1.f / l_i[i];
        float4 v = make_float4(acc[i][0] * inv, acc[i][1] * inv,
                               acc[i][2] * inv, acc[i][3] * inv);
        *(float4*)&out[((size_t)b * SEQ + q0 + ty * 4 + i) * HD + tx * 4] = v;
    }
}

// =====================================================================
extern "C" void kernel_launch(void* const* d_in, const int* in_sizes, int n_in,
                              void* d_out, int out_size) {
    const float* x  = (const float*)d_in[0];
    const float* Wk = (const float*)d_in[1];
    const float* Wq = (const float*)d_in[2];
    const float* Wv = (const float*)d_in[3];
    float* out = (float*)d_out;

    // Pass 1: QKV projections
    dim3 g1(MTOT / 64, 3);
    qkv_gemm<<<g1, 128>>>(x, Wq, Wk, Wv);

    // Pass 2: causal flash attention
    const int smem_bytes = (64 * 65 + 64 * 65 + 64 * 64) * (int)sizeof(float); // 49664
    cudaFuncSetAttribute((const void*)attn_kernel,
                         cudaFuncAttributeMaxDynamicSharedMemorySize, smem_bytes);
    attn_kernel<<<BATCH * (SEQ / 64), 256, smem_bytes>>>(out);
}

// round 5
// speedup vs baseline: 2.2303x; 2.2303x over previous
#include <cuda_runtime.h>
#include <cstdint>

#define BATCH 4
#define SEQ   4096
#define EMB   1024
#define HD    64
#define MTOT  (BATCH * SEQ)
#define MAXCHUNK 8

// ---------------- device scratch (no allocations allowed) ----------------
__device__ __align__(16) float g_Q [(size_t)MTOT * HD];
__device__ __align__(16) float g_K [(size_t)MTOT * HD];
__device__ __align__(16) float g_V [(size_t)MTOT * HD];
__device__ __align__(16) float g_Wt[3 * HD * EMB];                  // [t][h][k]
__device__ __align__(16) float g_Op[MAXCHUNK][(size_t)MTOT * HD];   // partial O
__device__ __align__(16) float g_lp[MAXCHUNK][MTOT];                // partial l

// ---------------- helpers ----------------
__device__ __forceinline__ uint32_t tf32r(float x) {
    uint32_t y; asm("cvt.rna.tf32.f32 %0, %1;" : "=r"(y) : "f"(x)); return y;
}
__device__ __forceinline__ float ex2f(float x) {
    float y; asm("ex2.approx.ftz.f32 %0, %1;" : "=f"(y) : "f"(x)); return y;
}
// D += A(16x8, tf32, row) * B(8x8, tf32, col)
__device__ __forceinline__ void mma8(float* d,
                                     uint32_t a0, uint32_t a1, uint32_t a2, uint32_t a3,
                                     uint32_t b0, uint32_t b1) {
    asm volatile(
        "mma.sync.aligned.m16n8k8.row.col.f32.tf32.tf32.f32 "
        "{%0,%1,%2,%3}, {%4,%5,%6,%7}, {%8,%9}, {%0,%1,%2,%3};"
        : "+f"(d[0]), "+f"(d[1]), "+f"(d[2]), "+f"(d[3])
        : "r"(a0), "r"(a1), "r"(a2), "r"(a3), "r"(b0), "r"(b1));
}

// =====================================================================
// Kernel 0: W transpose -> g_Wt[t][h][k]; fold (1/sqrt(E))*log2(e) into Wq.
// =====================================================================
__global__ __launch_bounds__(256) void wtrans_kernel(const float* __restrict__ Wk,
                                                     const float* __restrict__ Wq,
                                                     const float* __restrict__ Wv) {
    __shared__ float tile[64][65];
    const int t = blockIdx.x;
    const float* W = (t == 0) ? Wq : (t == 1) ? Wk : Wv;
    const float s = (t == 0) ? 0.03125f * 1.44269504088896340736f : 1.0f;
    const int k0 = blockIdx.y * 64;
    const int tid = threadIdx.x;
    for (int i = tid; i < 1024; i += 256) {
        int r = i >> 4, c = (i & 15) << 2;
        float4 v = *(const float4*)&W[(size_t)(k0 + r) * HD + c];
        tile[r][c] = v.x; tile[r][c + 1] = v.y; tile[r][c + 2] = v.z; tile[r][c + 3] = v.w;
    }
    __syncthreads();
    for (int i = tid; i < 4096; i += 256) {
        int h = i >> 6, kk = i & 63;
        g_Wt[(size_t)t * HD * EMB + (size_t)h * EMB + k0 + kk] = tile[kk][h] * s;
    }
}

// =====================================================================
// Kernel 1: projection via mma.sync tf32.  grid(3, MTOT/128).
// CTA: 128 rows x 64 cols for one of Q/K/V.  Warp = m16, 8 n-frags.
// =====================================================================
#define QK_PAD 40
__global__ __launch_bounds__(256) void qkv_kernel(const float* __restrict__ x) {
    __shared__ uint32_t Xs[128 * QK_PAD];
    __shared__ uint32_t Ws[64 * QK_PAD];
    const int t  = blockIdx.x;
    const int m0 = blockIdx.y * 128;
    const int tid = threadIdx.x, w = tid >> 5, lane = tid & 31;
    const int g = lane >> 2, tig = lane & 3;
    const float* Wt = g_Wt + (size_t)t * HD * EMB;

    float o[8][4];
#pragma unroll
    for (int n = 0; n < 8; n++)
#pragma unroll
        for (int j = 0; j < 4; j++) o[n][j] = 0.f;

    for (int kc = 0; kc < EMB; kc += 32) {
        __syncthreads();
        for (int i = tid; i < 1024; i += 256) {         // x chunk 128x32
            int r = i >> 3, c = (i & 7) << 2;
            float4 v = *(const float4*)&x[(size_t)(m0 + r) * EMB + kc + c];
            uint32_t* d = &Xs[r * QK_PAD + c];
            d[0] = tf32r(v.x); d[1] = tf32r(v.y); d[2] = tf32r(v.z); d[3] = tf32r(v.w);
        }
        for (int i = tid; i < 512; i += 256) {          // W chunk 64x32
            int r = i >> 3, c = (i & 7) << 2;
            float4 v = *(const float4*)&Wt[(size_t)r * EMB + kc + c];
            uint32_t* d = &Ws[r * QK_PAD + c];
            d[0] = tf32r(v.x); d[1] = tf32r(v.y); d[2] = tf32r(v.z); d[3] = tf32r(v.w);
        }
        __syncthreads();
#pragma unroll
        for (int k = 0; k < 4; k++) {
            const int kb = k << 3;
            const int ra = (w * 16 + g) * QK_PAD + kb;
            const int rb = (w * 16 + g + 8) * QK_PAD + kb;
            uint32_t a0 = Xs[ra + tig],     a1 = Xs[rb + tig];
            uint32_t a2 = Xs[ra + tig + 4], a3 = Xs[rb + tig + 4];
#pragma unroll
            for (int n = 0; n < 8; n++) {
                const int wb = (n * 8 + g) * QK_PAD + kb;
                mma8(o[n], a0, a1, a2, a3, Ws[wb + tig], Ws[wb + tig + 4]);
            }
        }
    }
    float* out = (t == 0) ? g_Q : (t == 1) ? g_K : g_V;
    const size_t r1 = (size_t)m0 + w * 16 + g, r2 = r1 + 8;
#pragma unroll
    for (int n = 0; n < 8; n++) {
        *(float2*)&out[r1 * HD + n * 8 + 2 * tig] = make_float2(o[n][0], o[n][1]);
        *(float2*)&out[r2 * HD + n * 8 + 2 * tig] = make_float2(o[n][2], o[n][3]);
    }
}

// =====================================================================
// Kernel 2: chunked causal flash attention (mma.sync tf32, no max-tracking).
// BM=128, BN=64. Work item = (b, qt, ci): chunk of <=8 n-blocks of 64.
// =====================================================================
#define AT_PAD 72
#define QOFF 0
#define KOFF (128 * AT_PAD)
#define VOFF (KOFF + 64 * AT_PAD)
#define POFF (VOFF + 64 * AT_PAD)
#define ATT_WORDS (POFF + 128 * AT_PAD)     // 27648 words = 110592 B

__global__ __launch_bounds__(256) void attn_kernel() {
    extern __shared__ uint32_t smu[];
    uint32_t* Qs = smu + QOFF;
    uint32_t* Ks = smu + KOFF;
    uint32_t* Vs = smu + VOFF;
    uint32_t* Ps = smu + POFF;

    const int bid = blockIdx.x;
    const int b = bid & 3;
    const int j = bid >> 2;
    int qt = 0, ci = 0;
    {
        int acc = 0;
        for (int q = 31; q >= 0; q--) {           // longest-first
            int nc = (2 * q + 9) >> 3;
            if (j < acc + nc) { qt = q; ci = j - acc; break; }
            acc += nc;
        }
    }
    const int q0 = qt << 7;
    const int blk0 = ci << 3;
    int blk1 = blk0 + 8;
    const int nb = 2 * qt + 2;
    if (blk1 > nb) blk1 = nb;

    const int tid = threadIdx.x, w = tid >> 5, lane = tid & 31;
    const int g = lane >> 2, tig = lane & 3;

    // Q tile 128x64 (scale folded into Wq already)
    const float* Qg = g_Q + ((size_t)b * SEQ + q0) * HD;
    for (int i = tid; i < 2048; i += 256) {
        int r = i >> 4, c = (i & 15) << 2;
        float4 v = *(const float4*)&Qg[(size_t)r * HD + c];
        uint32_t* d = &Qs[r * AT_PAD + c];
        d[0] = tf32r(v.x); d[1] = tf32r(v.y); d[2] = tf32r(v.z); d[3] = tf32r(v.w);
    }

    float o[8][4];
#pragma unroll
    for (int n = 0; n < 8; n++)
#pragma unroll
        for (int jj = 0; jj < 4; jj++) o[n][jj] = 0.f;
    float l1 = 0.f, l2 = 0.f;
    const int grow1 = q0 + w * 16 + g, grow2 = grow1 + 8;
    const float* Kg = g_K + (size_t)b * SEQ * HD;
    const float* Vg = g_V + (size_t)b * SEQ * HD;

    __syncthreads();
    for (int blk = blk0; blk < blk1; blk++) {
        const int n0 = blk << 6;
        for (int i = tid; i < 1024; i += 256) {   // K + V tiles 64x64
            int r = i >> 4, c = (i & 15) << 2;
            float4 v = *(const float4*)&Kg[(size_t)(n0 + r) * HD + c];
            uint32_t* d = &Ks[r * AT_PAD + c];
            d[0] = tf32r(v.x); d[1] = tf32r(v.y); d[2] = tf32r(v.z); d[3] = tf32r(v.w);
            float4 u = *(const float4*)&Vg[(size_t)(n0 + r) * HD + c];
            uint32_t* e = &Vs[r * AT_PAD + c];
            e[0] = tf32r(u.x); e[1] = tf32r(u.y); e[2] = tf32r(u.z); e[3] = tf32r(u.w);
        }
        __syncthreads();

        // S = Q K^T  (m16 per warp, n=64, k=64)
        float s[8][4];
#pragma unroll
        for (int n = 0; n < 8; n++)
#pragma unroll
            for (int jj = 0; jj < 4; jj++) s[n][jj] = 0.f;
#pragma unroll
        for (int k = 0; k < 8; k++) {
            const int kb = k << 3;
            const int ra = (w * 16 + g) * AT_PAD + kb;
            const int rb = (w * 16 + g + 8) * AT_PAD + kb;
            uint32_t a0 = Qs[ra + tig],     a1 = Qs[rb + tig];
            uint32_t a2 = Qs[ra + tig + 4], a3 = Qs[rb + tig + 4];
#pragma unroll
            for (int n = 0; n < 8; n++) {
                const int kbn = (n * 8 + g) * AT_PAD + kb;
                mma8(s[n], a0, a1, a2, a3, Ks[kbn + tig], Ks[kbn + tig + 4]);
            }
        }

        // softmax (exp2 domain); P -> smem (tf32)
        const bool diag = (blk >= 2 * qt);
#pragma unroll
        for (int n = 0; n < 8; n++) {
            const int cb = n0 + n * 8 + 2 * tig;
            float p0 = ex2f(s[n][0]), p1 = ex2f(s[n][1]);
            float p2 = ex2f(s[n][2]), p3 = ex2f(s[n][3]);
            if (diag) {
                if (cb     > grow1) p0 = 0.f;
                if (cb + 1 > grow1) p1 = 0.f;
                if (cb     > grow2) p2 = 0.f;
                if (cb + 1 > grow2) p3 = 0.f;
            }
            l1 += p0 + p1; l2 += p2 + p3;
            uint32_t* pr  = &Ps[(w * 16 + g) * AT_PAD + n * 8 + 2 * tig];
            pr[0] = tf32r(p0); pr[1] = tf32r(p1);
            uint32_t* pr2 = &Ps[(w * 16 + g + 8) * AT_PAD + n * 8 + 2 * tig];
            pr2[0] = tf32r(p2); pr2[1] = tf32r(p3);
        }
        __syncwarp();

        // O += P V  (k=64 over n-dim, n=64 over head dim)
#pragma unroll
        for (int kk = 0; kk < 8; kk++) {
            const int kb = kk << 3;
            const int ra = (w * 16 + g) * AT_PAD + kb;
            const int rb = (w * 16 + g + 8) * AT_PAD + kb;
            uint32_t a0 = Ps[ra + tig],     a1 = Ps[rb + tig];
            uint32_t a2 = Ps[ra + tig + 4], a3 = Ps[rb + tig + 4];
#pragma unroll
            for (int hh = 0; hh < 8; hh++) {
                uint32_t b0 = Vs[(kb + tig)     * AT_PAD + hh * 8 + g];
                uint32_t b1 = Vs[(kb + tig + 4) * AT_PAD + hh * 8 + g];
                mma8(o[hh], a0, a1, a2, a3, b0, b1);
            }
        }
        __syncthreads();   // all warps done with Ks/Vs before overwrite
    }

    // reduce l across the quad (cols are spread over tig)
    l1 += __shfl_xor_sync(0xffffffffu, l1, 1);
    l1 += __shfl_xor_sync(0xffffffffu, l1, 2);
    l2 += __shfl_xor_sync(0xffffffffu, l2, 1);
    l2 += __shfl_xor_sync(0xffffffffu, l2, 2);

    const size_t r1 = (size_t)b * SEQ + q0 + w * 16 + g, r2 = r1 + 8;
    float* dst = &g_Op[ci][0];
#pragma unroll
    for (int hh = 0; hh < 8; hh++) {
        *(float2*)&dst[r1 * HD + hh * 8 + 2 * tig] = make_float2(o[hh][0], o[hh][1]);
        *(float2*)&dst[r2 * HD + hh * 8 + 2 * tig] = make_float2(o[hh][2], o[hh][3]);
    }
    if (tig == 0) { g_lp[ci][r1] = l1; g_lp[ci][r2] = l2; }
}

// =====================================================================
// Kernel 3: merge partial slabs and normalize.
// =====================================================================
__global__ __launch_bounds__(256) void merge_kernel(float* __restrict__ out) {
    const int idx = blockIdx.x * 256 + threadIdx.x;   // float4 index
    const int m = idx >> 4;
    const int qt = (m & (SEQ - 1)) >> 7;
    const int nc = (2 * qt + 9) >> 3;
    float4 a = ((const float4*)&g_Op[0][0])[idx];
    float l = g_lp[0][m];
    for (int c = 1; c < nc; c++) {
        float4 t = ((const float4*)&g_Op[c][0])[idx];
        a.x += t.x; a.y += t.y; a.z += t.z; a.w += t.w;
        l += g_lp[c][m];
    }
    const float inv = 1.f / l;
    ((float4*)out)[idx] = make_float4(a.x * inv, a.y * inv, a.z * inv, a.w * inv);
}

// =====================================================================
extern "C" void kernel_launch(void* const* d_in, const int* in_sizes, int n_in,
                              void* d_out, int out_size) {
    const float* x  = (const float*)d_in[0];
    const float* Wk = (const float*)d_in[1];
    const float* Wq = (const float*)d_in[2];
    const float* Wv = (const float*)d_in[3];
    float* out = (float*)d_out;

    wtrans_kernel<<<dim3(3, 16), 256>>>(Wk, Wq, Wv);

    qkv_kernel<<<dim3(3, MTOT / 128), 256>>>(x);

    const int attn_smem = ATT_WORDS * 4;   // 110592 B
    cudaFuncSetAttribute((const void*)attn_kernel,
                         cudaFuncAttributeMaxDynamicSharedMemorySize, attn_smem);
    attn_kernel<<<576, 256, attn_smem>>>();

    merge_kernel<<<(MTOT * HD / 4) / 256, 256>>>(out);
}

// round 6
// speedup vs baseline: 2.8470x; 1.2765x over previous
#include <cuda_runtime.h>
#include <cstdint>

#define BATCH 4
#define SEQ   4096
#define EMB   1024
#define HD    64
#define MTOT  (BATCH * SEQ)
#define MAXCHUNK 8

// ---------------- device scratch (no allocations allowed) ----------------
__device__ __align__(16) float g_Q [(size_t)MTOT * HD];
__device__ __align__(16) float g_K [(size_t)MTOT * HD];
__device__ __align__(16) float g_V [(size_t)MTOT * HD];
__device__ __align__(16) float g_Wt[3 * HD * EMB];                  // [t][h][k]
__device__ __align__(16) float g_Op[MAXCHUNK][(size_t)MTOT * HD];   // partial O
__device__ __align__(16) float g_lp[MAXCHUNK][MTOT];                // partial l

// ---------------- helpers ----------------
__device__ __forceinline__ uint32_t tf32r(float x) {
    uint32_t y; asm("cvt.rna.tf32.f32 %0, %1;" : "=r"(y) : "f"(x)); return y;
}
__device__ __forceinline__ float ex2f(float x) {
    float y; asm("ex2.approx.ftz.f32 %0, %1;" : "=f"(y) : "f"(x)); return y;
}
// D += A(16x8, tf32, row) * B(8x8, tf32, col)
__device__ __forceinline__ void mma8(float* d,
                                     uint32_t a0, uint32_t a1, uint32_t a2, uint32_t a3,
                                     uint32_t b0, uint32_t b1) {
    asm volatile(
        "mma.sync.aligned.m16n8k8.row.col.f32.tf32.tf32.f32 "
        "{%0,%1,%2,%3}, {%4,%5,%6,%7}, {%8,%9}, {%0,%1,%2,%3};"
        : "+f"(d[0]), "+f"(d[1]), "+f"(d[2]), "+f"(d[3])
        : "r"(a0), "r"(a1), "r"(a2), "r"(a3), "r"(b0), "r"(b1));
}

// =====================================================================
// Kernel 0: W transpose -> g_Wt[t][h][k]; fold (1/sqrt(E))*log2(e) into Wq.
// =====================================================================
__global__ __launch_bounds__(256) void wtrans_kernel(const float* __restrict__ Wk,
                                                     const float* __restrict__ Wq,
                                                     const float* __restrict__ Wv) {
    __shared__ float tile[64][65];
    const int t = blockIdx.x;
    const float* W = (t == 0) ? Wq : (t == 1) ? Wk : Wv;
    const float s = (t == 0) ? 0.03125f * 1.44269504088896340736f : 1.0f;
    const int k0 = blockIdx.y * 64;
    const int tid = threadIdx.x;
    for (int i = tid; i < 1024; i += 256) {
        int r = i >> 4, c = (i & 15) << 2;
        float4 v = *(const float4*)&W[(size_t)(k0 + r) * HD + c];
        tile[r][c] = v.x; tile[r][c + 1] = v.y; tile[r][c + 2] = v.z; tile[r][c + 3] = v.w;
    }
    __syncthreads();
    for (int i = tid; i < 4096; i += 256) {
        int h = i >> 6, kk = i & 63;
        g_Wt[(size_t)t * HD * EMB + (size_t)h * EMB + k0 + kk] = tile[kk][h] * s;
    }
}

// =====================================================================
// Kernel 1: projection via mma.sync tf32.  grid(3, MTOT/128).
// CTA: 128 rows x 64 cols for one of Q/K/V. K-chunk = 64 (16 chunks).
// PAD=68 -> row stride = 4 mod 32 banks -> conflict-free fragment loads.
// =====================================================================
#define QK_PAD 68
#define QK_XW  (128 * QK_PAD)
#define QK_WORDS (QK_XW + 64 * QK_PAD)      // 13056 words = 52224 B

__global__ __launch_bounds__(256, 2) void qkv_kernel(const float* __restrict__ x) {
    extern __shared__ uint32_t smq[];
    uint32_t* Xs = smq;
    uint32_t* Ws = smq + QK_XW;
    const int t  = blockIdx.x;
    const int m0 = blockIdx.y * 128;
    const int tid = threadIdx.x, w = tid >> 5, lane = tid & 31;
    const int g = lane >> 2, tig = lane & 3;
    const float* Wt = g_Wt + (size_t)t * HD * EMB;

    float o[8][4];
#pragma unroll
    for (int n = 0; n < 8; n++)
#pragma unroll
        for (int j = 0; j < 4; j++) o[n][j] = 0.f;

    for (int kc = 0; kc < EMB; kc += 64) {
        __syncthreads();
        for (int i = tid; i < 2048; i += 256) {         // x chunk 128x64
            int r = i >> 4, c = (i & 15) << 2;
            float4 v = *(const float4*)&x[(size_t)(m0 + r) * EMB + kc + c];
            uint32_t* d = &Xs[r * QK_PAD + c];
            d[0] = tf32r(v.x); d[1] = tf32r(v.y); d[2] = tf32r(v.z); d[3] = tf32r(v.w);
        }
        for (int i = tid; i < 1024; i += 256) {         // W chunk 64x64
            int r = i >> 4, c = (i & 15) << 2;
            float4 v = *(const float4*)&Wt[(size_t)r * EMB + kc + c];
            uint32_t* d = &Ws[r * QK_PAD + c];
            d[0] = tf32r(v.x); d[1] = tf32r(v.y); d[2] = tf32r(v.z); d[3] = tf32r(v.w);
        }
        __syncthreads();
#pragma unroll
        for (int k = 0; k < 8; k++) {
            const int kb = k << 3;
            const int ra = (w * 16 + g) * QK_PAD + kb;
            const int rb = (w * 16 + g + 8) * QK_PAD + kb;
            uint32_t a0 = Xs[ra + tig],     a1 = Xs[rb + tig];
            uint32_t a2 = Xs[ra + tig + 4], a3 = Xs[rb + tig + 4];
#pragma unroll
            for (int n = 0; n < 8; n++) {
                const int wb = (n * 8 + g) * QK_PAD + kb;
                mma8(o[n], a0, a1, a2, a3, Ws[wb + tig], Ws[wb + tig + 4]);
            }
        }
    }
    float* out = (t == 0) ? g_Q : (t == 1) ? g_K : g_V;
    const size_t r1 = (size_t)m0 + w * 16 + g, r2 = r1 + 8;
#pragma unroll
    for (int n = 0; n < 8; n++) {
        *(float2*)&out[r1 * HD + n * 8 + 2 * tig] = make_float2(o[n][0], o[n][1]);
        *(float2*)&out[r2 * HD + n * 8 + 2 * tig] = make_float2(o[n][2], o[n][3]);
    }
}

// =====================================================================
// Kernel 2: chunked causal flash attention (mma.sync tf32, no max-tracking).
// BM=128, BN=64. Work item = (b, qt, ci): chunk of <=8 n-blocks of 64.
// Pads: Q/K/P = 68 (stride 4 mod 32 -> conflict-free row-major frags),
//       V = 72 (stride 8 mod 32 -> conflict-free [k][col] B-frags).
// smem 105.5 KB, __launch_bounds__(256,2) -> 2 CTAs/SM hide load latency.
// =====================================================================
#define RM_PAD 68
#define V_PAD  72
#define QOFF 0
#define KOFF (128 * RM_PAD)                  // 8704
#define VOFF (KOFF + 64 * RM_PAD)            // 13056
#define POFF (VOFF + 64 * V_PAD)             // 17664
#define ATT_WORDS (POFF + 128 * RM_PAD)      // 26368 words = 105472 B

__global__ __launch_bounds__(256, 2) void attn_kernel() {
    extern __shared__ uint32_t smu[];
    uint32_t* Qs = smu + QOFF;
    uint32_t* Ks = smu + KOFF;
    uint32_t* Vs = smu + VOFF;
    uint32_t* Ps = smu + POFF;

    const int bid = blockIdx.x;
    const int b = bid & 3;
    const int j = bid >> 2;
    int qt = 0, ci = 0;
    {
        int acc = 0;
        for (int q = 31; q >= 0; q--) {           // longest-first
            int nc = (2 * q + 9) >> 3;
            if (j < acc + nc) { qt = q; ci = j - acc; break; }
            acc += nc;
        }
    }
    const int q0 = qt << 7;
    const int blk0 = ci << 3;
    int blk1 = blk0 + 8;
    const int nb = 2 * qt + 2;
    if (blk1 > nb) blk1 = nb;

    const int tid = threadIdx.x, w = tid >> 5, lane = tid & 31;
    const int g = lane >> 2, tig = lane & 3;

    // Q tile 128x64 (scale folded into Wq already)
    const float* Qg = g_Q + ((size_t)b * SEQ + q0) * HD;
    for (int i = tid; i < 2048; i += 256) {
        int r = i >> 4, c = (i & 15) << 2;
        float4 v = *(const float4*)&Qg[(size_t)r * HD + c];
        uint32_t* d = &Qs[r * RM_PAD + c];
        d[0] = tf32r(v.x); d[1] = tf32r(v.y); d[2] = tf32r(v.z); d[3] = tf32r(v.w);
    }

    float o[8][4];
#pragma unroll
    for (int n = 0; n < 8; n++)
#pragma unroll
        for (int jj = 0; jj < 4; jj++) o[n][jj] = 0.f;
    float l1 = 0.f, l2 = 0.f;
    const int grow1 = q0 + w * 16 + g, grow2 = grow1 + 8;
    const float* Kg = g_K + (size_t)b * SEQ * HD;
    const float* Vg = g_V + (size_t)b * SEQ * HD;

    __syncthreads();
    for (int blk = blk0; blk < blk1; blk++) {
        const int n0 = blk << 6;
        for (int i = tid; i < 1024; i += 256) {   // K + V tiles 64x64
            int r = i >> 4, c = (i & 15) << 2;
            float4 v = *(const float4*)&Kg[(size_t)(n0 + r) * HD + c];
            uint32_t* d = &Ks[r * RM_PAD + c];
            d[0] = tf32r(v.x); d[1] = tf32r(v.y); d[2] = tf32r(v.z); d[3] = tf32r(v.w);
            float4 u = *(const float4*)&Vg[(size_t)(n0 + r) * HD + c];
            uint32_t* e = &Vs[r * V_PAD + c];
            e[0] = tf32r(u.x); e[1] = tf32r(u.y); e[2] = tf32r(u.z); e[3] = tf32r(u.w);
        }
        __syncthreads();

        // S = Q K^T  (m16 per warp, n=64, k=64)
        float s[8][4];
#pragma unroll
        for (int n = 0; n < 8; n++)
#pragma unroll
            for (int jj = 0; jj < 4; jj++) s[n][jj] = 0.f;
#pragma unroll
        for (int k = 0; k < 8; k++) {
            const int kb = k << 3;
            const int ra = (w * 16 + g) * RM_PAD + kb;
            const int rb = (w * 16 + g + 8) * RM_PAD + kb;
            uint32_t a0 = Qs[ra + tig],     a1 = Qs[rb + tig];
            uint32_t a2 = Qs[ra + tig + 4], a3 = Qs[rb + tig + 4];
#pragma unroll
            for (int n = 0; n < 8; n++) {
                const int kbn = (n * 8 + g) * RM_PAD + kb;
                mma8(s[n], a0, a1, a2, a3, Ks[kbn + tig], Ks[kbn + tig + 4]);
            }
        }

        // softmax (exp2 domain); P -> smem (tf32)
        const bool diag = (blk >= 2 * qt);
#pragma unroll
        for (int n = 0; n < 8; n++) {
            const int cb = n0 + n * 8 + 2 * tig;
            float p0 = ex2f(s[n][0]), p1 = ex2f(s[n][1]);
            float p2 = ex2f(s[n][2]), p3 = ex2f(s[n][3]);
            if (diag) {
                if (cb     > grow1) p0 = 0.f;
                if (cb + 1 > grow1) p1 = 0.f;
                if (cb     > grow2) p2 = 0.f;
                if (cb + 1 > grow2) p3 = 0.f;
            }
            l1 += p0 + p1; l2 += p2 + p3;
            uint32_t* pr  = &Ps[(w * 16 + g) * RM_PAD + n * 8 + 2 * tig];
            pr[0] = tf32r(p0); pr[1] = tf32r(p1);
            uint32_t* pr2 = &Ps[(w * 16 + g + 8) * RM_PAD + n * 8 + 2 * tig];
            pr2[0] = tf32r(p2); pr2[1] = tf32r(p3);
        }
        __syncwarp();

        // O += P V  (k=64 over n-dim, n=64 over head dim)
#pragma unroll
        for (int kk = 0; kk < 8; kk++) {
            const int kb = kk << 3;
            const int ra = (w * 16 + g) * RM_PAD + kb;
            const int rb = (w * 16 + g + 8) * RM_PAD + kb;
            uint32_t a0 = Ps[ra + tig],     a1 = Ps[rb + tig];
            uint32_t a2 = Ps[ra + tig + 4], a3 = Ps[rb + tig + 4];
#pragma unroll
            for (int hh = 0; hh < 8; hh++) {
                uint32_t b0 = Vs[(kb + tig)     * V_PAD + hh * 8 + g];
                uint32_t b1 = Vs[(kb + tig + 4) * V_PAD + hh * 8 + g];
                mma8(o[hh], a0, a1, a2, a3, b0, b1);
            }
        }
        __syncthreads();   // all warps done with Ks/Vs before overwrite
    }

    // reduce l across the quad (cols are spread over tig)
    l1 += __shfl_xor_sync(0xffffffffu, l1, 1);
    l1 += __shfl_xor_sync(0xffffffffu, l1, 2);
    l2 += __shfl_xor_sync(0xffffffffu, l2, 1);
    l2 += __shfl_xor_sync(0xffffffffu, l2, 2);

    const size_t r1 = (size_t)b * SEQ + q0 + w * 16 + g, r2 = r1 + 8;
    float* dst = &g_Op[ci][0];
#pragma unroll
    for (int hh = 0; hh < 8; hh++) {
        *(float2*)&dst[r1 * HD + hh * 8 + 2 * tig] = make_float2(o[hh][0], o[hh][1]);
        *(float2*)&dst[r2 * HD + hh * 8 + 2 * tig] = make_float2(o[hh][2], o[hh][3]);
    }
    if (tig == 0) { g_lp[ci][r1] = l1; g_lp[ci][r2] = l2; }
}

// =====================================================================
// Kernel 3: merge partial slabs and normalize.
// =====================================================================
__global__ __launch_bounds__(256) void merge_kernel(float* __restrict__ out) {
    const int idx = blockIdx.x * 256 + threadIdx.x;   // float4 index
    const int m = idx >> 4;
    const int qt = (m & (SEQ - 1)) >> 7;
    const int nc = (2 * qt + 9) >> 3;
    float4 a = ((const float4*)&g_Op[0][0])[idx];
    float l = g_lp[0][m];
    for (int c = 1; c < nc; c++) {
        float4 t = ((const float4*)&g_Op[c][0])[idx];
        a.x += t.x; a.y += t.y; a.z += t.z; a.w += t.w;
        l += g_lp[c][m];
    }
    const float inv = 1.f / l;
    ((float4*)out)[idx] = make_float4(a.x * inv, a.y * inv, a.z * inv, a.w * inv);
}

// =====================================================================
extern "C" void kernel_launch(void* const* d_in, const int* in_sizes, int n_in,
                              void* d_out, int out_size) {
    const float* x  = (const float*)d_in[0];
    const float* Wk = (const float*)d_in[1];
    const float* Wq = (const float*)d_in[2];
    const float* Wv = (const float*)d_in[3];
    float* out = (float*)d_out;

    wtrans_kernel<<<dim3(3, 16), 256>>>(Wk, Wq, Wv);

    const int qkv_smem = QK_WORDS * 4;     // 52224 B
    cudaFuncSetAttribute((const void*)qkv_kernel,
                         cudaFuncAttributeMaxDynamicSharedMemorySize, qkv_smem);
    qkv_kernel<<<dim3(3, MTOT / 128), 256, qkv_smem>>>(x);

    const int attn_smem = ATT_WORDS * 4;   // 105472 B
    cudaFuncSetAttribute((const void*)attn_kernel,
                         cudaFuncAttributeMaxDynamicSharedMemorySize, attn_smem);
    attn_kernel<<<576, 256, attn_smem>>>();

    merge_kernel<<<(MTOT * HD / 4) / 256, 256>>>(out);
}

// round 7
// speedup vs baseline: 2.9475x; 1.0353x over previous
#include <cuda_runtime.h>
#include <cstdint>

#define BATCH 4
#define SEQ   4096
#define EMB   1024
#define HD    64
#define MTOT  (BATCH * SEQ)
#define MAXCHUNK 8

// ---------------- device scratch (no allocations allowed) ----------------
// g_Q/g_K/g_V hold tf32-rounded (rna) bit patterns stored as float.
__device__ __align__(16) float g_Q [(size_t)MTOT * HD];
__device__ __align__(16) float g_K [(size_t)MTOT * HD];
__device__ __align__(16) float g_V [(size_t)MTOT * HD];
__device__ __align__(16) float g_Wt[3 * HD * EMB];                  // [t][h][k]
__device__ __align__(16) float g_Op[MAXCHUNK][(size_t)MTOT * HD];   // partial O
__device__ __align__(16) float g_lp[MAXCHUNK][MTOT];                // partial l

// ---------------- helpers ----------------
__device__ __forceinline__ uint32_t tf32r(float x) {
    uint32_t y; asm("cvt.rna.tf32.f32 %0, %1;" : "=r"(y) : "f"(x)); return y;
}
__device__ __forceinline__ float ex2f(float x) {
    float y; asm("ex2.approx.ftz.f32 %0, %1;" : "=f"(y) : "f"(x)); return y;
}
__device__ __forceinline__ uint32_t smem_u32(const void* p) {
    uint32_t a;
    asm("{ .reg .u64 t; cvta.to.shared.u64 t, %1; cvt.u32.u64 %0, t; }" : "=r"(a) : "l"(p));
    return a;
}
__device__ __forceinline__ void cpa16(uint32_t dst, const float* src) {
    asm volatile("cp.async.cg.shared.global [%0], [%1], 16;" :: "r"(dst), "l"(src) : "memory");
}
#define CP_COMMIT() asm volatile("cp.async.commit_group;" ::: "memory")
#define CP_WAIT(n)  asm volatile("cp.async.wait_group %0;" :: "n"(n) : "memory")

// D += A(16x8, tf32, row) * B(8x8, tf32, col)
__device__ __forceinline__ void mma8(float* d,
                                     uint32_t a0, uint32_t a1, uint32_t a2, uint32_t a3,
                                     uint32_t b0, uint32_t b1) {
    asm volatile(
        "mma.sync.aligned.m16n8k8.row.col.f32.tf32.tf32.f32 "
        "{%0,%1,%2,%3}, {%4,%5,%6,%7}, {%8,%9}, {%0,%1,%2,%3};"
        : "+f"(d[0]), "+f"(d[1]), "+f"(d[2]), "+f"(d[3])
        : "r"(a0), "r"(a1), "r"(a2), "r"(a3), "r"(b0), "r"(b1));
}

// =====================================================================
// Kernel 0: W transpose -> g_Wt[t][h][k]; fold (1/sqrt(E))*log2(e) into Wq.
// =====================================================================
__global__ __launch_bounds__(256) void wtrans_kernel(const float* __restrict__ Wk,
                                                     const float* __restrict__ Wq,
                                                     const float* __restrict__ Wv) {
    __shared__ float tile[64][65];
    const int t = blockIdx.x;
    const float* W = (t == 0) ? Wq : (t == 1) ? Wk : Wv;
    const float s = (t == 0) ? 0.03125f * 1.44269504088896340736f : 1.0f;
    const int k0 = blockIdx.y * 64;
    const int tid = threadIdx.x;
    for (int i = tid; i < 1024; i += 256) {
        int r = i >> 4, c = (i & 15) << 2;
        float4 v = *(const float4*)&W[(size_t)(k0 + r) * HD + c];
        tile[r][c] = v.x; tile[r][c + 1] = v.y; tile[r][c + 2] = v.z; tile[r][c + 3] = v.w;
    }
    __syncthreads();
    for (int i = tid; i < 4096; i += 256) {
        int h = i >> 6, kk = i & 63;
        g_Wt[(size_t)t * HD * EMB + (size_t)h * EMB + k0 + kk] = tile[kk][h] * s;
    }
}

// =====================================================================
// Kernel 1: projection via mma.sync tf32.  grid(3, MTOT/128).
// Epilogue stores tf32-rounded bit patterns (so attention can copy raw).
// =====================================================================
#define QK_PAD 68
#define QK_XW  (128 * QK_PAD)
#define QK_WORDS (QK_XW + 64 * QK_PAD)      // 13056 words = 52224 B

__global__ __launch_bounds__(256, 2) void qkv_kernel(const float* __restrict__ x) {
    extern __shared__ uint32_t smq[];
    uint32_t* Xs = smq;
    uint32_t* Ws = smq + QK_XW;
    const int t  = blockIdx.x;
    const int m0 = blockIdx.y * 128;
    const int tid = threadIdx.x, w = tid >> 5, lane = tid & 31;
    const int g = lane >> 2, tig = lane & 3;
    const float* Wt = g_Wt + (size_t)t * HD * EMB;

    float o[8][4];
#pragma unroll
    for (int n = 0; n < 8; n++)
#pragma unroll
        for (int j = 0; j < 4; j++) o[n][j] = 0.f;

    for (int kc = 0; kc < EMB; kc += 64) {
        __syncthreads();
        for (int i = tid; i < 2048; i += 256) {         // x chunk 128x64
            int r = i >> 4, c = (i & 15) << 2;
            float4 v = *(const float4*)&x[(size_t)(m0 + r) * EMB + kc + c];
            uint32_t* d = &Xs[r * QK_PAD + c];
            d[0] = tf32r(v.x); d[1] = tf32r(v.y); d[2] = tf32r(v.z); d[3] = tf32r(v.w);
        }
        for (int i = tid; i < 1024; i += 256) {         // W chunk 64x64
            int r = i >> 4, c = (i & 15) << 2;
            float4 v = *(const float4*)&Wt[(size_t)r * EMB + kc + c];
            uint32_t* d = &Ws[r * QK_PAD + c];
            d[0] = tf32r(v.x); d[1] = tf32r(v.y); d[2] = tf32r(v.z); d[3] = tf32r(v.w);
        }
        __syncthreads();
#pragma unroll
        for (int k = 0; k < 8; k++) {
            const int kb = k << 3;
            const int ra = (w * 16 + g) * QK_PAD + kb;
            const int rb = (w * 16 + g + 8) * QK_PAD + kb;
            uint32_t a0 = Xs[ra + tig],     a1 = Xs[rb + tig];
            uint32_t a2 = Xs[ra + tig + 4], a3 = Xs[rb + tig + 4];
#pragma unroll
            for (int n = 0; n < 8; n++) {
                const int wb = (n * 8 + g) * QK_PAD + kb;
                mma8(o[n], a0, a1, a2, a3, Ws[wb + tig], Ws[wb + tig + 4]);
            }
        }
    }
    float* out = (t == 0) ? g_Q : (t == 1) ? g_K : g_V;
    const size_t r1 = (size_t)m0 + w * 16 + g, r2 = r1 + 8;
#pragma unroll
    for (int n = 0; n < 8; n++) {
        *(float2*)&out[r1 * HD + n * 8 + 2 * tig] =
            make_float2(__uint_as_float(tf32r(o[n][0])), __uint_as_float(tf32r(o[n][1])));
        *(float2*)&out[r2 * HD + n * 8 + 2 * tig] =
            make_float2(__uint_as_float(tf32r(o[n][2])), __uint_as_float(tf32r(o[n][3])));
    }
}

// =====================================================================
// Kernel 2: chunked causal flash attention (mma.sync tf32, no max-tracking).
// BM=128, BN=64. Q A-frags in registers; K/V double-buffered via cp.async;
// P passed C-layout -> A-layout via warp shuffles (no smem round-trip).
// smem = 2 x (K 64x68 + V 64x72) = 17920 words = 70 KB -> 2 CTAs/SM.
// =====================================================================
#define K_PAD 68
#define V_PAD 72
#define KV_BUF (64 * K_PAD + 64 * V_PAD)     // 8960 words per stage
#define ATT_WORDS (2 * KV_BUF)               // 17920 words = 71680 B

__device__ __forceinline__ void load_kv_async(uint32_t sb, int buf,
                                              const float* Kg, const float* Vg,
                                              int n0, int tid) {
    const uint32_t kb = sb + buf * (KV_BUF * 4);
    const uint32_t vb = kb + 64 * K_PAD * 4;
#pragma unroll
    for (int t = 0; t < 4; t++) {
        int i = t * 256 + tid;                 // 1024 float4 for K
        int r = i >> 4, c4 = (i & 15) << 2;
        cpa16(kb + (r * K_PAD + c4) * 4, Kg + (size_t)(n0 + r) * HD + c4);
    }
#pragma unroll
    for (int t = 0; t < 4; t++) {
        int i = t * 256 + tid;                 // 1024 float4 for V
        int r = i >> 4, c4 = (i & 15) << 2;
        cpa16(vb + (r * V_PAD + c4) * 4, Vg + (size_t)(n0 + r) * HD + c4);
    }
}

__global__ __launch_bounds__(256, 2) void attn_kernel() {
    extern __shared__ uint32_t smu[];
    const uint32_t sb = smem_u32(smu);

    const int bid = blockIdx.x;
    const int b = bid & 3;
    const int j = bid >> 2;
    int qt = 0, ci = 0;
    {
        int acc = 0;
        for (int q = 31; q >= 0; q--) {           // longest-first
            int nc = (2 * q + 9) >> 3;
            if (j < acc + nc) { qt = q; ci = j - acc; break; }
            acc += nc;
        }
    }
    const int q0 = qt << 7;
    const int blk0 = ci << 3;
    int blk1 = blk0 + 8;
    const int nb = 2 * qt + 2;
    if (blk1 > nb) blk1 = nb;

    const int tid = threadIdx.x, w = tid >> 5, lane = tid & 31;
    const int g = lane >> 2, tig = lane & 3;

    const float* Qg = g_Q + ((size_t)b * SEQ + q0) * HD;
    const float* Kg = g_K + (size_t)b * SEQ * HD;
    const float* Vg = g_V + (size_t)b * SEQ * HD;

    // ---- prologue: stage Q through smem once, keep A-frags in registers ----
    for (int i = tid; i < 2048; i += 256) {       // 128x64 raw copy (already tf32 bits)
        int r = i >> 4, c = (i & 15) << 2;
        *(float4*)&smu[r * K_PAD + c] = *(const float4*)&Qg[(size_t)r * HD + c];
    }
    __syncthreads();
    uint32_t qa[8][4];
    {
        const int ra = (w * 16 + g) * K_PAD;
        const int rb = ra + 8 * K_PAD;
#pragma unroll
        for (int k = 0; k < 8; k++) {
            const int kb = k << 3;
            qa[k][0] = smu[ra + kb + tig];
            qa[k][1] = smu[rb + kb + tig];
            qa[k][2] = smu[ra + kb + tig + 4];
            qa[k][3] = smu[rb + kb + tig + 4];
        }
    }
    __syncthreads();

    // first K/V stage
    load_kv_async(sb, 0, Kg, Vg, blk0 << 6, tid);
    CP_COMMIT();

    float o[8][4];
#pragma unroll
    for (int n = 0; n < 8; n++)
#pragma unroll
        for (int jj = 0; jj < 4; jj++) o[n][jj] = 0.f;
    float l1 = 0.f, l2 = 0.f;
    const int grow1 = q0 + w * 16 + g, grow2 = grow1 + 8;
    const int srcA = (lane & 28) | (tig >> 1);
    const int srcB = srcA + 2;
    const bool oddt = (tig & 1);

    for (int blk = blk0; blk < blk1; blk++) {
        const int cur = (blk - blk0) & 1;
        if (blk + 1 < blk1) {
            load_kv_async(sb, cur ^ 1, Kg, Vg, (blk + 1) << 6, tid);
            CP_COMMIT();
            CP_WAIT(1);
        } else {
            CP_WAIT(0);
        }
        __syncthreads();

        const uint32_t* Ks = smu + cur * KV_BUF;
        const uint32_t* Vs = Ks + 64 * K_PAD;
        const int n0 = blk << 6;

        // S = Q K^T  (m16 per warp, n=64, k=64); Q from registers
        float s[8][4];
#pragma unroll
        for (int n = 0; n < 8; n++)
#pragma unroll
            for (int jj = 0; jj < 4; jj++) s[n][jj] = 0.f;
#pragma unroll
        for (int k = 0; k < 8; k++) {
            const int kb = k << 3;
#pragma unroll
            for (int n = 0; n < 8; n++) {
                const int kbn = (n * 8 + g) * K_PAD + kb;
                mma8(s[n], qa[k][0], qa[k][1], qa[k][2], qa[k][3],
                     Ks[kbn + tig], Ks[kbn + tig + 4]);
            }
        }

        // softmax (exp2 domain); store tf32-rounded P bits back into s
        const bool diag = (blk >= 2 * qt);
#pragma unroll
        for (int n = 0; n < 8; n++) {
            const int cb = n0 + n * 8 + 2 * tig;
            float p0 = ex2f(s[n][0]), p1 = ex2f(s[n][1]);
            float p2 = ex2f(s[n][2]), p3 = ex2f(s[n][3]);
            if (diag) {
                if (cb     > grow1) p0 = 0.f;
                if (cb + 1 > grow1) p1 = 0.f;
                if (cb     > grow2) p2 = 0.f;
                if (cb + 1 > grow2) p3 = 0.f;
            }
            l1 += p0 + p1; l2 += p2 + p3;
            s[n][0] = __uint_as_float(tf32r(p0));
            s[n][1] = __uint_as_float(tf32r(p1));
            s[n][2] = __uint_as_float(tf32r(p2));
            s[n][3] = __uint_as_float(tf32r(p3));
        }

        // O += P V : A-frags of P via shuffles (C-layout -> A-layout)
#pragma unroll
        for (int kk = 0; kk < 8; kk++) {
            const uint32_t c0 = __float_as_uint(s[kk][0]);
            const uint32_t c1 = __float_as_uint(s[kk][1]);
            const uint32_t c2 = __float_as_uint(s[kk][2]);
            const uint32_t c3 = __float_as_uint(s[kk][3]);
            const uint32_t s0a = __shfl_sync(0xffffffffu, c0, srcA);
            const uint32_t s1a = __shfl_sync(0xffffffffu, c1, srcA);
            const uint32_t s2a = __shfl_sync(0xffffffffu, c2, srcA);
            const uint32_t s3a = __shfl_sync(0xffffffffu, c3, srcA);
            const uint32_t s0b = __shfl_sync(0xffffffffu, c0, srcB);
            const uint32_t s1b = __shfl_sync(0xffffffffu, c1, srcB);
            const uint32_t s2b = __shfl_sync(0xffffffffu, c2, srcB);
            const uint32_t s3b = __shfl_sync(0xffffffffu, c3, srcB);
            const uint32_t a0 = oddt ? s1a : s0a;
            const uint32_t a1 = oddt ? s3a : s2a;
            const uint32_t a2 = oddt ? s1b : s0b;
            const uint32_t a3 = oddt ? s3b : s2b;
            const int kr0 = (kk * 8 + tig) * V_PAD;
            const int kr1 = (kk * 8 + tig + 4) * V_PAD;
#pragma unroll
            for (int hh = 0; hh < 8; hh++) {
                mma8(o[hh], a0, a1, a2, a3,
                     Vs[kr0 + hh * 8 + g], Vs[kr1 + hh * 8 + g]);
            }
        }
        __syncthreads();   // all warps done with this stage before its reuse
    }

    // reduce l across the quad (cols are spread over tig)
    l1 += __shfl_xor_sync(0xffffffffu, l1, 1);
    l1 += __shfl_xor_sync(0xffffffffu, l1, 2);
    l2 += __shfl_xor_sync(0xffffffffu, l2, 1);
    l2 += __shfl_xor_sync(0xffffffffu, l2, 2);

    const size_t r1 = (size_t)b * SEQ + q0 + w * 16 + g, r2 = r1 + 8;
    float* dst = &g_Op[ci][0];
#pragma unroll
    for (int hh = 0; hh < 8; hh++) {
        *(float2*)&dst[r1 * HD + hh * 8 + 2 * tig] = make_float2(o[hh][0], o[hh][1]);
        *(float2*)&dst[r2 * HD + hh * 8 + 2 * tig] = make_float2(o[hh][2], o[hh][3]);
    }
    if (tig == 0) { g_lp[ci][r1] = l1; g_lp[ci][r2] = l2; }
}

// =====================================================================
// Kernel 3: merge partial slabs and normalize.
// =====================================================================
__global__ __launch_bounds__(256) void merge_kernel(float* __restrict__ out) {
    const int idx = blockIdx.x * 256 + threadIdx.x;   // float4 index
    const int m = idx >> 4;
    const int qt = (m & (SEQ - 1)) >> 7;
    const int nc = (2 * qt + 9) >> 3;
    float4 a = ((const float4*)&g_Op[0][0])[idx];
    float l = g_lp[0][m];
    for (int c = 1; c < nc; c++) {
        float4 t = ((const float4*)&g_Op[c][0])[idx];
        a.x += t.x; a.y += t.y; a.z += t.z; a.w += t.w;
        l += g_lp[c][m];
    }
    const float inv = 1.f / l;
    ((float4*)out)[idx] = make_float4(a.x * inv, a.y * inv, a.z * inv, a.w * inv);
}

// =====================================================================
extern "C" void kernel_launch(void* const* d_in, const int* in_sizes, int n_in,
                              void* d_out, int out_size) {
    const float* x  = (const float*)d_in[0];
    const float* Wk = (const float*)d_in[1];
    const float* Wq = (const float*)d_in[2];
    const float* Wv = (const float*)d_in[3];
    float* out = (float*)d_out;

    wtrans_kernel<<<dim3(3, 16), 256>>>(Wk, Wq, Wv);

    const int qkv_smem = QK_WORDS * 4;     // 52224 B
    cudaFuncSetAttribute((const void*)qkv_kernel,
                         cudaFuncAttributeMaxDynamicSharedMemorySize, qkv_smem);
    qkv_kernel<<<dim3(3, MTOT / 128), 256, qkv_smem>>>(x);

    const int attn_smem = ATT_WORDS * 4;   // 71680 B
    cudaFuncSetAttribute((const void*)attn_kernel,
                         cudaFuncAttributeMaxDynamicSharedMemorySize, attn_smem);
    attn_kernel<<<576, 256, attn_smem>>>();

    merge_kernel<<<(MTOT * HD / 4) / 256, 256>>>(out);
}

// round 8
// speedup vs baseline: 5.1118x; 1.7343x over previous
#include <cuda_runtime.h>
#include <cuda_fp16.h>
#include <cstdint>

#define BATCH 4
#define SEQ   4096
#define EMB   1024
#define HD    64
#define MTOT  (BATCH * SEQ)
#define MAXCHUNK 8

// ---------------- device scratch (no allocations allowed) ----------------
__device__ __align__(16) __half g_Qh [(size_t)MTOT * HD];            // [t][h], qscale folded
__device__ __align__(16) __half g_Kh [(size_t)MTOT * HD];            // [t][h]
__device__ __align__(16) __half g_Vth[(size_t)BATCH * HD * SEQ];     // [b][h][t] (transposed)
__device__ __align__(16) float  g_Wt [3 * HD * EMB];                 // [t][h][k]
__device__ __align__(16) float  g_Op [MAXCHUNK][(size_t)MTOT * HD];  // partial O
__device__ __align__(16) float  g_lp [MAXCHUNK][MTOT];               // partial l

// ---------------- helpers ----------------
__device__ __forceinline__ float ex2f(float x) {
    float y; asm("ex2.approx.ftz.f32 %0, %1;" : "=f"(y) : "f"(x)); return y;
}
__device__ __forceinline__ uint32_t pk(float lo, float hi) {
    __half2 h = __floats2half2_rn(lo, hi);
    return *(uint32_t*)&h;
}
__device__ __forceinline__ uint32_t smem_u32(const void* p) {
    uint32_t a;
    asm("{ .reg .u64 t; cvta.to.shared.u64 t, %1; cvt.u32.u64 %0, t; }" : "=r"(a) : "l"(p));
    return a;
}
__device__ __forceinline__ void cpa16(uint32_t dst, const void* src) {
    asm volatile("cp.async.cg.shared.global [%0], [%1], 16;" :: "r"(dst), "l"(src) : "memory");
}
#define CP_COMMIT() asm volatile("cp.async.commit_group;" ::: "memory")
#define CP_WAIT(n)  asm volatile("cp.async.wait_group %0;" :: "n"(n) : "memory")

// D(f32) += A(16x16 f16, row) * B(16x8 f16, col)
__device__ __forceinline__ void mma16(float* d,
                                      uint32_t a0, uint32_t a1, uint32_t a2, uint32_t a3,
                                      uint32_t b0, uint32_t b1) {
    asm volatile(
        "mma.sync.aligned.m16n8k16.row.col.f32.f16.f16.f32 "
        "{%0,%1,%2,%3}, {%4,%5,%6,%7}, {%8,%9}, {%0,%1,%2,%3};"
        : "+f"(d[0]), "+f"(d[1]), "+f"(d[2]), "+f"(d[3])
        : "r"(a0), "r"(a1), "r"(a2), "r"(a3), "r"(b0), "r"(b1));
}

// =====================================================================
// Kernel 0: W transpose -> g_Wt[t][h][k]; fold (1/sqrt(E))*log2(e) into Wq.
// =====================================================================
__global__ __launch_bounds__(256) void wtrans_kernel(const float* __restrict__ Wk,
                                                     const float* __restrict__ Wq,
                                                     const float* __restrict__ Wv) {
    __shared__ float tile[64][65];
    const int t = blockIdx.x;
    const float* W = (t == 0) ? Wq : (t == 1) ? Wk : Wv;
    const float s = (t == 0) ? 0.03125f * 1.44269504088896340736f : 1.0f;
    const int k0 = blockIdx.y * 64;
    const int tid = threadIdx.x;
    for (int i = tid; i < 1024; i += 256) {
        int r = i >> 4, c = (i & 15) << 2;
        float4 v = *(const float4*)&W[(size_t)(k0 + r) * HD + c];
        tile[r][c] = v.x; tile[r][c + 1] = v.y; tile[r][c + 2] = v.z; tile[r][c + 3] = v.w;
    }
    __syncthreads();
    for (int i = tid; i < 4096; i += 256) {
        int h = i >> 6, kk = i & 63;
        g_Wt[(size_t)t * HD * EMB + (size_t)h * EMB + k0 + kk] = tile[kk][h] * s;
    }
}

// =====================================================================
// Kernel 1: projection via mma.sync fp16 (f32 accum).  grid(3, MTOT/128).
// smem tiles as fp16x2 words, PAD=36 (stride 4 mod 32 -> conflict-free).
// Outputs fp16: Q/K natural [t][h]; V transposed [b][h][t].
// =====================================================================
#define HPAD 36
#define QK_XW (128 * HPAD)
#define QK_WORDS (QK_XW + 64 * HPAD)        // 6912 words = 27648 B

__global__ __launch_bounds__(256, 3) void qkv_kernel(const float* __restrict__ x) {
    extern __shared__ uint32_t smq[];
    uint32_t* Xs = smq;
    uint32_t* Ws = smq + QK_XW;
    const int t  = blockIdx.x;
    const int m0 = blockIdx.y * 128;
    const int tid = threadIdx.x, w = tid >> 5, lane = tid & 31;
    const int g = lane >> 2, tig = lane & 3;
    const float* Wt = g_Wt + (size_t)t * HD * EMB;

    float o[8][4];
#pragma unroll
    for (int n = 0; n < 8; n++)
#pragma unroll
        for (int j = 0; j < 4; j++) o[n][j] = 0.f;

    for (int kc = 0; kc < EMB; kc += 64) {
        __syncthreads();
        for (int i = tid; i < 2048; i += 256) {         // x chunk 128x64 -> fp16
            int r = i >> 4, c4 = i & 15;
            float4 v = *(const float4*)&x[(size_t)(m0 + r) * EMB + kc + c4 * 4];
            Xs[r * HPAD + c4 * 2]     = pk(v.x, v.y);
            Xs[r * HPAD + c4 * 2 + 1] = pk(v.z, v.w);
        }
        for (int i = tid; i < 1024; i += 256) {         // W chunk 64x64 -> fp16
            int r = i >> 4, c4 = i & 15;
            float4 v = *(const float4*)&Wt[(size_t)r * EMB + kc + c4 * 4];
            Ws[r * HPAD + c4 * 2]     = pk(v.x, v.y);
            Ws[r * HPAD + c4 * 2 + 1] = pk(v.z, v.w);
        }
        __syncthreads();
#pragma unroll
        for (int kk = 0; kk < 4; kk++) {
            const int kb = kk << 3;
            const int ra = (w * 16 + g) * HPAD + kb;
            const int rb = ra + 8 * HPAD;
            uint32_t a0 = Xs[ra + tig],     a1 = Xs[rb + tig];
            uint32_t a2 = Xs[ra + tig + 4], a3 = Xs[rb + tig + 4];
#pragma unroll
            for (int n = 0; n < 8; n++) {
                const int wb = (n * 8 + g) * HPAD + kb;
                mma16(o[n], a0, a1, a2, a3, Ws[wb + tig], Ws[wb + tig + 4]);
            }
        }
    }

    const int r1 = m0 + w * 16 + g, r2 = r1 + 8;
    if (t < 2) {
        __half* out = (t == 0) ? g_Qh : g_Kh;
#pragma unroll
        for (int n = 0; n < 8; n++) {
            *(__half2*)&out[(size_t)r1 * HD + n * 8 + 2 * tig] = __floats2half2_rn(o[n][0], o[n][1]);
            *(__half2*)&out[(size_t)r2 * HD + n * 8 + 2 * tig] = __floats2half2_rn(o[n][2], o[n][3]);
        }
    } else {
        const int bb = r1 >> 12;
        const int t1 = r1 & 4095, t2 = t1 + 8;
        __half* vt = g_Vth + (size_t)bb * HD * SEQ;
#pragma unroll
        for (int n = 0; n < 8; n++) {
            const int h0 = n * 8 + 2 * tig;
            vt[(size_t)h0 * SEQ + t1]       = __float2half_rn(o[n][0]);
            vt[(size_t)(h0 + 1) * SEQ + t1] = __float2half_rn(o[n][1]);
            vt[(size_t)h0 * SEQ + t2]       = __float2half_rn(o[n][2]);
            vt[(size_t)(h0 + 1) * SEQ + t2] = __float2half_rn(o[n][3]);
        }
    }
}

// =====================================================================
// Kernel 2: chunked causal flash attention (mma.sync fp16, no max-tracking).
// BM=128, BN=64. Q A-frags in regs; K/V^T double-buffered via cp.async;
// S->P fragment layout is the identity (4 packs per k-step, no shuffles).
// smem = 2 x (K 64x36w + V 64x36w) = 9216 words = 36864 B -> 2 CTAs/SM.
// =====================================================================
#define KV_BUF (2 * 64 * HPAD)               // 4608 words per stage
#define ATT_WORDS (2 * KV_BUF)               // 9216 words

__device__ __forceinline__ void load_kv_async(uint32_t sb, int buf,
                                              const __half* Kg, const __half* Vt,
                                              int n0, int tid) {
    const uint32_t kb = sb + buf * (KV_BUF * 4);
    const uint32_t vb = kb + 64 * HPAD * 4;
#pragma unroll
    for (int it = 0; it < 2; it++) {
        int i = it * 256 + tid;                 // 512 chunks of 16B for K
        int r = i >> 3, c4 = i & 7;
        cpa16(kb + (r * HPAD + c4 * 4) * 4, Kg + (size_t)(n0 + r) * HD + c4 * 8);
    }
#pragma unroll
    for (int it = 0; it < 2; it++) {
        int i = it * 256 + tid;                 // 512 chunks of 16B for V^T
        int r = i >> 3, c4 = i & 7;
        cpa16(vb + (r * HPAD + c4 * 4) * 4, Vt + (size_t)r * SEQ + n0 + c4 * 8);
    }
}

__global__ __launch_bounds__(256, 2) void attn_kernel() {
    extern __shared__ uint32_t smu[];
    const uint32_t sb = smem_u32(smu);

    const int bid = blockIdx.x;
    const int b = bid & 3;
    const int j = bid >> 2;
    int qt = 0, ci = 0;
    {
        int acc = 0;
        for (int q = 31; q >= 0; q--) {           // longest-first
            int nc = (2 * q + 9) >> 3;
            if (j < acc + nc) { qt = q; ci = j - acc; break; }
            acc += nc;
        }
    }
    const int q0 = qt << 7;
    const int blk0 = ci << 3;
    int blk1 = blk0 + 8;
    const int nb = 2 * qt + 2;
    if (blk1 > nb) blk1 = nb;

    const int tid = threadIdx.x, w = tid >> 5, lane = tid & 31;
    const int g = lane >> 2, tig = lane & 3;

    const __half* Qg = g_Qh + ((size_t)b * SEQ + q0) * HD;
    const __half* Kg = g_Kh + (size_t)b * SEQ * HD;
    const __half* Vt = g_Vth + (size_t)b * HD * SEQ;

    // ---- prologue: stage Q through smem once, keep A-frags in registers ----
    for (int i = tid; i < 1024; i += 256) {       // 128 rows x 8 uint4
        int r = i >> 3, c4 = i & 7;
        *(uint4*)&smu[r * HPAD + c4 * 4] = *(const uint4*)&Qg[(size_t)r * HD + c4 * 8];
    }
    __syncthreads();
    uint32_t qa[4][4];
    {
        const int ra = (w * 16 + g) * HPAD;
        const int rb = ra + 8 * HPAD;
#pragma unroll
        for (int kk = 0; kk < 4; kk++) {
            const int kb = kk << 3;
            qa[kk][0] = smu[ra + kb + tig];
            qa[kk][1] = smu[rb + kb + tig];
            qa[kk][2] = smu[ra + kb + tig + 4];
            qa[kk][3] = smu[rb + kb + tig + 4];
        }
    }
    __syncthreads();

    load_kv_async(sb, 0, Kg, Vt, blk0 << 6, tid);
    CP_COMMIT();

    float o[8][4];
#pragma unroll
    for (int n = 0; n < 8; n++)
#pragma unroll
        for (int jj = 0; jj < 4; jj++) o[n][jj] = 0.f;
    float l1 = 0.f, l2 = 0.f;
    const int grow1 = q0 + w * 16 + g, grow2 = grow1 + 8;

    for (int blk = blk0; blk < blk1; blk++) {
        const int cur = (blk - blk0) & 1;
        if (blk + 1 < blk1) {
            load_kv_async(sb, cur ^ 1, Kg, Vt, (blk + 1) << 6, tid);
            CP_COMMIT();
            CP_WAIT(1);
        } else {
            CP_WAIT(0);
        }
        __syncthreads();

        const uint32_t* Ks = smu + cur * KV_BUF;
        const uint32_t* Vs = Ks + 64 * HPAD;
        const int n0 = blk << 6;

        // S = Q K^T  (m16 per warp, n=64, k=64); Q from registers
        float s[8][4];
#pragma unroll
        for (int n = 0; n < 8; n++)
#pragma unroll
            for (int jj = 0; jj < 4; jj++) s[n][jj] = 0.f;
#pragma unroll
        for (int kk = 0; kk < 4; kk++) {
            const int kb = kk << 3;
#pragma unroll
            for (int n = 0; n < 8; n++) {
                const int kbn = (n * 8 + g) * HPAD + kb;
                mma16(s[n], qa[kk][0], qa[kk][1], qa[kk][2], qa[kk][3],
                      Ks[kbn + tig], Ks[kbn + tig + 4]);
            }
        }

        // softmax (exp2 domain); result left in s as f32
        const bool diag = (blk >= 2 * qt);
#pragma unroll
        for (int n = 0; n < 8; n++) {
            const int cb = n0 + n * 8 + 2 * tig;
            float p0 = ex2f(s[n][0]), p1 = ex2f(s[n][1]);
            float p2 = ex2f(s[n][2]), p3 = ex2f(s[n][3]);
            if (diag) {
                if (cb     > grow1) p0 = 0.f;
                if (cb + 1 > grow1) p1 = 0.f;
                if (cb     > grow2) p2 = 0.f;
                if (cb + 1 > grow2) p3 = 0.f;
            }
            l1 += p0 + p1; l2 += p2 + p3;
            s[n][0] = p0; s[n][1] = p1; s[n][2] = p2; s[n][3] = p3;
        }

        // O += P V : identity C->A layout, 4 packs per k-step, no shuffles
#pragma unroll
        for (int kk = 0; kk < 4; kk++) {
            const uint32_t a0 = pk(s[2 * kk][0],     s[2 * kk][1]);
            const uint32_t a1 = pk(s[2 * kk][2],     s[2 * kk][3]);
            const uint32_t a2 = pk(s[2 * kk + 1][0], s[2 * kk + 1][1]);
            const uint32_t a3 = pk(s[2 * kk + 1][2], s[2 * kk + 1][3]);
            const int kb = kk << 3;
#pragma unroll
            for (int hh = 0; hh < 8; hh++) {
                const int vr = (hh * 8 + g) * HPAD + kb;
                mma16(o[hh], a0, a1, a2, a3, Vs[vr + tig], Vs[vr + tig + 4]);
            }
        }
        __syncthreads();   // all warps done with this stage before reuse
    }

    // reduce l across the quad (cols are spread over tig)
    l1 += __shfl_xor_sync(0xffffffffu, l1, 1);
    l1 += __shfl_xor_sync(0xffffffffu, l1, 2);
    l2 += __shfl_xor_sync(0xffffffffu, l2, 1);
    l2 += __shfl_xor_sync(0xffffffffu, l2, 2);

    const size_t r1 = (size_t)b * SEQ + q0 + w * 16 + g, r2 = r1 + 8;
    float* dst = &g_Op[ci][0];
#pragma unroll
    for (int hh = 0; hh < 8; hh++) {
        *(float2*)&dst[r1 * HD + hh * 8 + 2 * tig] = make_float2(o[hh][0], o[hh][1]);
        *(float2*)&dst[r2 * HD + hh * 8 + 2 * tig] = make_float2(o[hh][2], o[hh][3]);
    }
    if (tig == 0) { g_lp[ci][r1] = l1; g_lp[ci][r2] = l2; }
}

// =====================================================================
// Kernel 3: merge partial slabs and normalize.
// =====================================================================
__global__ __launch_bounds__(256) void merge_kernel(float* __restrict__ out) {
    const int idx = blockIdx.x * 256 + threadIdx.x;   // float4 index
    const int m = idx >> 4;
    const int qt = (m & (SEQ - 1)) >> 7;
    const int nc = (2 * qt + 9) >> 3;
    float4 a = ((const float4*)&g_Op[0][0])[idx];
    float l = g_lp[0][m];
    for (int c = 1; c < nc; c++) {
        float4 t = ((const float4*)&g_Op[c][0])[idx];
        a.x += t.x; a.y += t.y; a.z += t.z; a.w += t.w;
        l += g_lp[c][m];
    }
    const float inv = 1.f / l;
    ((float4*)out)[idx] = make_float4(a.x * inv, a.y * inv, a.z * inv, a.w * inv);
}

// =====================================================================
extern "C" void kernel_launch(void* const* d_in, const int* in_sizes, int n_in,
                              void* d_out, int out_size) {
    const float* x  = (const float*)d_in[0];
    const float* Wk = (const float*)d_in[1];
    const float* Wq = (const float*)d_in[2];
    const float* Wv = (const float*)d_in[3];
    float* out = (float*)d_out;

    wtrans_kernel<<<dim3(3, 16), 256>>>(Wk, Wq, Wv);

    const int qkv_smem = QK_WORDS * 4;     // 27648 B
    qkv_kernel<<<dim3(3, MTOT / 128), 256, qkv_smem>>>(x);

    const int attn_smem = ATT_WORDS * 4;   // 36864 B
    attn_kernel<<<576, 256, attn_smem>>>();

    merge_kernel<<<(MTOT * HD / 4) / 256, 256>>>(out);
}

// round 10
// speedup vs baseline: 5.2188x; 1.0209x over previous
#include <cuda_runtime.h>
#include <cuda_fp16.h>
#include <cstdint>

#define BATCH 4
#define SEQ   4096
#define EMB   1024
#define HD    64
#define MTOT  (BATCH * SEQ)
#define MAXCHUNK 8

// ---------------- device scratch (no allocations allowed) ----------------
__device__ __align__(16) __half g_Qh [(size_t)MTOT * HD];            // [t][h], qscale folded
__device__ __align__(16) __half g_Kh [(size_t)MTOT * HD];            // [t][h]
__device__ __align__(16) __half g_Vth[(size_t)BATCH * HD * SEQ];     // [b][h][t] (transposed)
__device__ __align__(16) float  g_Wt [3 * HD * EMB];                 // [t][h][k]
__device__ __align__(16) float  g_Op [MAXCHUNK][(size_t)MTOT * HD];  // partial O
__device__ __align__(16) float  g_lp [MAXCHUNK][MTOT];               // partial l

// ---------------- helpers ----------------
__device__ __forceinline__ uint32_t pk(float lo, float hi) {
    __half2 h = __floats2half2_rn(lo, hi);
    return *(uint32_t*)&h;
}
__device__ __forceinline__ uint32_t h2ex2(uint32_t x) {
    uint32_t y; asm("ex2.approx.f16x2 %0, %1;" : "=r"(y) : "r"(x)); return y;
}
__device__ __forceinline__ float neg_inf() { return __int_as_float(0xff800000); }
__device__ __forceinline__ uint32_t smem_u32(const void* p) {
    uint32_t a;
    asm("{ .reg .u64 t; cvta.to.shared.u64 t, %1; cvt.u32.u64 %0, t; }" : "=r"(a) : "l"(p));
    return a;
}
__device__ __forceinline__ void cpa16(uint32_t dst, const void* src) {
    asm volatile("cp.async.cg.shared.global [%0], [%1], 16;" :: "r"(dst), "l"(src) : "memory");
}
#define CP_COMMIT() asm volatile("cp.async.commit_group;" ::: "memory")
#define CP_WAIT(n)  asm volatile("cp.async.wait_group %0;" :: "n"(n) : "memory")

// D(f32) += A(16x16 f16, row) * B(16x8 f16, col)
__device__ __forceinline__ void mma16(float* d,
                                      uint32_t a0, uint32_t a1, uint32_t a2, uint32_t a3,
                                      uint32_t b0, uint32_t b1) {
    asm volatile(
        "mma.sync.aligned.m16n8k16.row.col.f32.f16.f16.f32 "
        "{%0,%1,%2,%3}, {%4,%5,%6,%7}, {%8,%9}, {%0,%1,%2,%3};"
        : "+f"(d[0]), "+f"(d[1]), "+f"(d[2]), "+f"(d[3])
        : "r"(a0), "r"(a1), "r"(a2), "r"(a3), "r"(b0), "r"(b1));
}

// =====================================================================
// Kernel 0: W transpose -> g_Wt[t][h][k]; fold (1/sqrt(E))*log2(e) into Wq.
// =====================================================================
__global__ __launch_bounds__(256) void wtrans_kernel(const float* __restrict__ Wk,
                                                     const float* __restrict__ Wq,
                                                     const float* __restrict__ Wv) {
    __shared__ float tile[64][65];
    const int t = blockIdx.x;
    const float* W = (t == 0) ? Wq : (t == 1) ? Wk : Wv;
    const float s = (t == 0) ? 0.03125f * 1.44269504088896340736f : 1.0f;
    const int k0 = blockIdx.y * 64;
    const int tid = threadIdx.x;
    for (int i = tid; i < 1024; i += 256) {
        int r = i >> 4, c = (i & 15) << 2;
        float4 v = *(const float4*)&W[(size_t)(k0 + r) * HD + c];
        tile[r][c] = v.x; tile[r][c + 1] = v.y; tile[r][c + 2] = v.z; tile[r][c + 3] = v.w;
    }
    __syncthreads();
    for (int i = tid; i < 4096; i += 256) {
        int h = i >> 6, kk = i & 63;
        g_Wt[(size_t)t * HD * EMB + (size_t)h * EMB + k0 + kk] = tile[kk][h] * s;
    }
}

// =====================================================================
// Kernel 1: projection via mma.sync fp16 (f32 accum).  grid(3, MTOT/128).
// =====================================================================
#define HPAD 36
#define QK_XW (128 * HPAD)
#define QK_WORDS (QK_XW + 64 * HPAD)        // 6912 words = 27648 B

__global__ __launch_bounds__(256, 3) void qkv_kernel(const float* __restrict__ x) {
    extern __shared__ uint32_t smq[];
    uint32_t* Xs = smq;
    uint32_t* Ws = smq + QK_XW;
    const int t  = blockIdx.x;
    const int m0 = blockIdx.y * 128;
    const int tid = threadIdx.x, w = tid >> 5, lane = tid & 31;
    const int g = lane >> 2, tig = lane & 3;
    const float* Wt = g_Wt + (size_t)t * HD * EMB;

    float o[8][4];
#pragma unroll
    for (int n = 0; n < 8; n++)
#pragma unroll
        for (int j = 0; j < 4; j++) o[n][j] = 0.f;

    for (int kc = 0; kc < EMB; kc += 64) {
        __syncthreads();
        for (int i = tid; i < 2048; i += 256) {         // x chunk 128x64 -> fp16
            int r = i >> 4, c4 = i & 15;
            float4 v = *(const float4*)&x[(size_t)(m0 + r) * EMB + kc + c4 * 4];
            Xs[r * HPAD + c4 * 2]     = pk(v.x, v.y);
            Xs[r * HPAD + c4 * 2 + 1] = pk(v.z, v.w);
        }
        for (int i = tid; i < 1024; i += 256) {         // W chunk 64x64 -> fp16
            int r = i >> 4, c4 = i & 15;
            float4 v = *(const float4*)&Wt[(size_t)r * EMB + kc + c4 * 4];
            Ws[r * HPAD + c4 * 2]     = pk(v.x, v.y);
            Ws[r * HPAD + c4 * 2 + 1] = pk(v.z, v.w);
        }
        __syncthreads();
#pragma unroll
        for (int kk = 0; kk < 4; kk++) {
            const int kb = kk << 3;
            const int ra = (w * 16 + g) * HPAD + kb;
            const int rb = ra + 8 * HPAD;
            uint32_t a0 = Xs[ra + tig],     a1 = Xs[rb + tig];
            uint32_t a2 = Xs[ra + tig + 4], a3 = Xs[rb + tig + 4];
#pragma unroll
            for (int n = 0; n < 8; n++) {
                const int wb = (n * 8 + g) * HPAD + kb;
                mma16(o[n], a0, a1, a2, a3, Ws[wb + tig], Ws[wb + tig + 4]);
            }
        }
    }

    const int r1 = m0 + w * 16 + g, r2 = r1 + 8;
    if (t < 2) {
        __half* out = (t == 0) ? g_Qh : g_Kh;
#pragma unroll
        for (int n = 0; n < 8; n++) {
            *(__half2*)&out[(size_t)r1 * HD + n * 8 + 2 * tig] = __floats2half2_rn(o[n][0], o[n][1]);
            *(__half2*)&out[(size_t)r2 * HD + n * 8 + 2 * tig] = __floats2half2_rn(o[n][2], o[n][3]);
        }
    } else {
        const int bb = r1 >> 12;
        const int t1 = r1 & 4095, t2 = t1 + 8;
        __half* vt = g_Vth + (size_t)bb * HD * SEQ;
#pragma unroll
        for (int n = 0; n < 8; n++) {
            const int h0 = n * 8 + 2 * tig;
            vt[(size_t)h0 * SEQ + t1]       = __float2half_rn(o[n][0]);
            vt[(size_t)(h0 + 1) * SEQ + t1] = __float2half_rn(o[n][1]);
            vt[(size_t)h0 * SEQ + t2]       = __float2half_rn(o[n][2]);
            vt[(size_t)(h0 + 1) * SEQ + t2] = __float2half_rn(o[n][3]);
        }
    }
}

// =====================================================================
// Kernel 2: chunked causal flash attention (mma.sync fp16).
// fp16x2 softmax (ex2.approx.f16x2); l via ones-column MMA (exact f32 sums
// of the same fp16 P the PV mma consumes). 3-stage cp.async pipeline with
// ONE __syncthreads per iteration. smem = 3 x 4608 words = 55296 B.
// =====================================================================
#define KV_BUF (2 * 64 * HPAD)               // 4608 words per stage
#define NSTAGE 3
#define ATT_WORDS (NSTAGE * KV_BUF)

__device__ __forceinline__ void load_kv_async(uint32_t sb, int buf,
                                              const __half* Kg, const __half* Vt,
                                              int n0, int tid) {
    const uint32_t kb = sb + buf * (KV_BUF * 4);
    const uint32_t vb = kb + 64 * HPAD * 4;
#pragma unroll
    for (int it = 0; it < 2; it++) {
        int i = it * 256 + tid;                 // 512 chunks of 16B for K
        int r = i >> 3, c4 = i & 7;
        cpa16(kb + (r * HPAD + c4 * 4) * 4, Kg + (size_t)(n0 + r) * HD + c4 * 8);
    }
#pragma unroll
    for (int it = 0; it < 2; it++) {
        int i = it * 256 + tid;                 // 512 chunks of 16B for V^T
        int r = i >> 3, c4 = i & 7;
        cpa16(vb + (r * HPAD + c4 * 4) * 4, Vt + (size_t)r * SEQ + n0 + c4 * 8);
    }
}

__global__ __launch_bounds__(256, 2) void attn_kernel() {
    extern __shared__ uint32_t smu[];
    const uint32_t sb = smem_u32(smu);

    const int bid = blockIdx.x;
    const int b = bid & 3;
    const int j = bid >> 2;
    int qt = 0, ci = 0;
    {
        int acc = 0;
        for (int q = 31; q >= 0; q--) {           // longest-first
            int nc = (2 * q + 9) >> 3;
            if (j < acc + nc) { qt = q; ci = j - acc; break; }
            acc += nc;
        }
    }
    const int q0 = qt << 7;
    const int blk0 = ci << 3;
    int blk1 = blk0 + 8;
    const int nb = 2 * qt + 2;
    if (blk1 > nb) blk1 = nb;

    const int tid = threadIdx.x, w = tid >> 5, lane = tid & 31;
    const int g = lane >> 2, tig = lane & 3;

    const __half* Qg = g_Qh + ((size_t)b * SEQ + q0) * HD;
    const __half* Kg = g_Kh + (size_t)b * SEQ * HD;
    const __half* Vt = g_Vth + (size_t)b * HD * SEQ;

    // ---- prologue: stage Q through smem once, keep A-frags in registers ----
    for (int i = tid; i < 1024; i += 256) {       // 128 rows x 8 uint4
        int r = i >> 3, c4 = i & 7;
        *(uint4*)&smu[r * HPAD + c4 * 4] = *(const uint4*)&Qg[(size_t)r * HD + c4 * 8];
    }
    __syncthreads();
    uint32_t qa[4][4];
    {
        const int ra = (w * 16 + g) * HPAD;
        const int rb = ra + 8 * HPAD;
#pragma unroll
        for (int kk = 0; kk < 4; kk++) {
            const int kb = kk << 3;
            qa[kk][0] = smu[ra + kb + tig];
            qa[kk][1] = smu[rb + kb + tig];
            qa[kk][2] = smu[ra + kb + tig + 4];
            qa[kk][3] = smu[rb + kb + tig + 4];
        }
    }
    __syncthreads();

    // 3-stage pipeline prologue (one commit per stage; empty commits OK)
    load_kv_async(sb, 0, Kg, Vt, blk0 << 6, tid);
    CP_COMMIT();
    if (blk0 + 1 < blk1) load_kv_async(sb, 1, Kg, Vt, (blk0 + 1) << 6, tid);
    CP_COMMIT();

    float o[8][4];
#pragma unroll
    for (int n = 0; n < 8; n++)
#pragma unroll
        for (int jj = 0; jj < 4; jj++) o[n][jj] = 0.f;
    float lacc[4] = {0.f, 0.f, 0.f, 0.f};
    const uint32_t ONES2 = 0x3C003C00u;          // (1.0h, 1.0h)
    const int grow1 = q0 + w * 16 + g, grow2 = grow1 + 8;

    for (int blk = blk0; blk < blk1; blk++) {
        const int cur = (blk - blk0) % NSTAGE;
        CP_WAIT(1);            // all but newest group done -> stage cur ready
        __syncthreads();       // data visible; stage (cur+2)%3 free for reuse
        if (blk + 2 < blk1) load_kv_async(sb, (cur + 2) % NSTAGE, Kg, Vt, (blk + 2) << 6, tid);
        CP_COMMIT();           // exactly one group per iteration

        const uint32_t* Ks = smu + cur * KV_BUF;
        const uint32_t* Vs = Ks + 64 * HPAD;
        const int n0 = blk << 6;

        // S = Q K^T  (m16 per warp, n=64, k=64); Q from registers
        float s[8][4];
#pragma unroll
        for (int n = 0; n < 8; n++)
#pragma unroll
            for (int jj = 0; jj < 4; jj++) s[n][jj] = 0.f;
#pragma unroll
        for (int kk = 0; kk < 4; kk++) {
            const int kb = kk << 3;
#pragma unroll
            for (int n = 0; n < 8; n++) {
                const int kbn = (n * 8 + g) * HPAD + kb;
                mma16(s[n], qa[kk][0], qa[kk][1], qa[kk][2], qa[kk][3],
                      Ks[kbn + tig], Ks[kbn + tig + 4]);
            }
        }

        // mask (diag only), then fp16x2 exp2 -> P directly as A-fragments
        if (blk >= 2 * qt) {
#pragma unroll
            for (int n = 0; n < 8; n++) {
                const int cb = n0 + n * 8 + 2 * tig;
                if (cb     > grow1) s[n][0] = neg_inf();
                if (cb + 1 > grow1) s[n][1] = neg_inf();
                if (cb     > grow2) s[n][2] = neg_inf();
                if (cb + 1 > grow2) s[n][3] = neg_inf();
            }
        }
        uint32_t u1[8], u2[8];
#pragma unroll
        for (int n = 0; n < 8; n++) {
            u1[n] = h2ex2(pk(s[n][0], s[n][1]));   // row1 pair
            u2[n] = h2ex2(pk(s[n][2], s[n][3]));   // row2 pair
        }

        // l accumulation + O += P V
#pragma unroll
        for (int kk = 0; kk < 4; kk++) {
            const uint32_t a0 = u1[2 * kk],     a1 = u2[2 * kk];
            const uint32_t a2 = u1[2 * kk + 1], a3 = u2[2 * kk + 1];
            mma16(lacc, a0, a1, a2, a3, ONES2, ONES2);   // row sums (exact, f32)
            const int kb = kk << 3;
#pragma unroll
            for (int hh = 0; hh < 8; hh++) {
                const int vr = (hh * 8 + g) * HPAD + kb;
                mma16(o[hh], a0, a1, a2, a3, Vs[vr + tig], Vs[vr + tig + 4]);
            }
        }
    }

    // lacc[0] = full row1 sum, lacc[2] = full row2 sum (k summed inside mma)
    const size_t r1 = (size_t)b * SEQ + q0 + w * 16 + g, r2 = r1 + 8;
    float* dst = &g_Op[ci][0];
#pragma unroll
    for (int hh = 0; hh < 8; hh++) {
        *(float2*)&dst[r1 * HD + hh * 8 + 2 * tig] = make_float2(o[hh][0], o[hh][1]);
        *(float2*)&dst[r2 * HD + hh * 8 + 2 * tig] = make_float2(o[hh][2], o[hh][3]);
    }
    if (tig == 0) { g_lp[ci][r1] = lacc[0]; g_lp[ci][r2] = lacc[2]; }
}

// =====================================================================
// Kernel 3: merge partial slabs and normalize.
// =====================================================================
__global__ __launch_bounds__(256) void merge_kernel(float* __restrict__ out) {
    const int idx = blockIdx.x * 256 + threadIdx.x;   // float4 index
    const int m = idx >> 4;
    const int qt = (m & (SEQ - 1)) >> 7;
    const int nc = (2 * qt + 9) >> 3;
    float4 a = ((const float4*)&g_Op[0][0])[idx];
    float l = g_lp[0][m];
    for (int c = 1; c < nc; c++) {
        float4 t = ((const float4*)&g_Op[c][0])[idx];
        a.x += t.x; a.y += t.y; a.z += t.z; a.w += t.w;
        l += g_lp[c][m];
    }
    const float inv = 1.f / l;
    ((float4*)out)[idx] = make_float4(a.x * inv, a.y * inv, a.z * inv, a.w * inv);
}

// =====================================================================
extern "C" void kernel_launch(void* const* d_in, const int* in_sizes, int n_in,
                              void* d_out, int out_size) {
    const float* x  = (const float*)d_in[0];
    const float* Wk = (const float*)d_in[1];
    const float* Wq = (const float*)d_in[2];
    const float* Wv = (const float*)d_in[3];
    float* out = (float*)d_out;

    // Opt-in smem limits (R8 failure: 55296 B > 49152 B default; launch was
    // rejected before capture). Host-side attribute set, capture-legal.
    cudaFuncSetAttribute((const void*)attn_kernel,
                         cudaFuncAttributeMaxDynamicSharedMemorySize, ATT_WORDS * 4);

    wtrans_kernel<<<dim3(3, 16), 256>>>(Wk, Wq, Wv);

    const int qkv_smem = QK_WORDS * 4;     // 27648 B
    qkv_kernel<<<dim3(3, MTOT / 128), 256, qkv_smem>>>(x);

    const int attn_smem = ATT_WORDS * 4;   // 55296 B
    attn_kernel<<<576, 256, attn_smem>>>();

    merge_kernel<<<(MTOT * HD / 4) / 256, 256>>>(out);
}